// round 3
// baseline (speedup 1.0000x reference)
#include <cuda_runtime.h>
#include <math.h>

#define CS 1024
#define CZ 128
#define NH 16
#define HD 64
#define NI 1024
#define NJ 1024

// ---------------- scratch (device globals; no allocation allowed) ----------------
__device__ float g_q[NI * CS];
__device__ float g_k[NJ * CS];
__device__ float g_v[NJ * CS];
__device__ float g_g[NI * CS];
__device__ float g_o[NI * CS];
__device__ float g_z[(size_t)NH * NI * NJ];   // 64 MB

// ---------------- GEMM: C[m][n] = act( sum_k A[m][k] * W[n][k] (+bias[n]) ) ----------
// MODE: 0 = plain, 1 = +bias vector, 2 = sigmoid
// MUL: A is elementwise-multiplied by A2 at load time (for g (*) o)
// BM=128, BN=64, BK=16, 256 threads (tx=16 over n, ty=16 over m), microtile 8m x 4n
template <int MODE, bool MUL>
__global__ __launch_bounds__(256) void gemm_xwT(
    const float* __restrict__ A, const float* __restrict__ A2,
    const float* __restrict__ W, const float* __restrict__ bvec,
    float* __restrict__ C)
{
    const int K = CS, N = CS;
    __shared__ float As[16][129];
    __shared__ float Bs[16][65];

    const int tid = threadIdx.x;
    const int tx = tid & 15;
    const int ty = tid >> 4;
    const int m0 = blockIdx.y * 128;
    const int n0 = blockIdx.x * 64;

    float acc[8][4];
#pragma unroll
    for (int r = 0; r < 8; r++)
#pragma unroll
        for (int c = 0; c < 4; c++) acc[r][c] = 0.f;

    for (int k0 = 0; k0 < K; k0 += 16) {
        // A tile: 128 x 16 floats = 512 float4, 2 per thread
#pragma unroll
        for (int p = 0; p < 2; p++) {
            int slot = tid + 256 * p;
            int m = slot >> 2;
            int k4 = slot & 3;
            float4 av = *(const float4*)(A + (size_t)(m0 + m) * K + k0 + k4 * 4);
            if (MUL) {
                float4 a2 = *(const float4*)(A2 + (size_t)(m0 + m) * K + k0 + k4 * 4);
                av.x *= a2.x; av.y *= a2.y; av.z *= a2.z; av.w *= a2.w;
            }
            As[k4 * 4 + 0][m] = av.x;
            As[k4 * 4 + 1][m] = av.y;
            As[k4 * 4 + 2][m] = av.z;
            As[k4 * 4 + 3][m] = av.w;
        }
        // B tile: 64 x 16 floats = 256 float4, 1 per thread
        {
            int n = tid >> 2;
            int k4 = tid & 3;
            float4 bv = *(const float4*)(W + (size_t)(n0 + n) * K + k0 + k4 * 4);
            Bs[k4 * 4 + 0][n] = bv.x;
            Bs[k4 * 4 + 1][n] = bv.y;
            Bs[k4 * 4 + 2][n] = bv.z;
            Bs[k4 * 4 + 3][n] = bv.w;
        }
        __syncthreads();

#pragma unroll
        for (int k = 0; k < 16; k++) {
            float a[8], b[4];
#pragma unroll
            for (int r = 0; r < 8; r++) a[r] = As[k][ty + 16 * r];
#pragma unroll
            for (int c = 0; c < 4; c++) b[c] = Bs[k][tx + 16 * c];
#pragma unroll
            for (int r = 0; r < 8; r++)
#pragma unroll
                for (int c = 0; c < 4; c++) acc[r][c] += a[r] * b[c];
        }
        __syncthreads();
    }

#pragma unroll
    for (int r = 0; r < 8; r++) {
        int m = m0 + ty + 16 * r;
#pragma unroll
        for (int c = 0; c < 4; c++) {
            int n = n0 + tx + 16 * c;
            float vv = acc[r][c];
            if (MODE == 1) vv += bvec[n];
            if (MODE == 2) vv = 1.f / (1.f + __expf(-vv));
            C[(size_t)m * N + n] = vv;
        }
    }
}

// ---------------- z kernel: z[h,i,j] = sum_c bias[i,j,c]*Wz[c,h] + (1-mask[j])*(-1e6)
// Block: 256 threads = (ig:2) x (jg:32) x (hg:4). Tile: 2 i-rows x 256 j x 16 h.
// c processed in chunks of 32 through smem. Each thread: 8 j x 4 h accumulators.
#define ZB_SMEM ((2 * 256 * 33 + CZ * NH) * 4)
__global__ __launch_bounds__(256) void zbias_kernel(
    const float* __restrict__ bias, const float* __restrict__ Wz,
    const float* __restrict__ mask, float* __restrict__ z)
{
    extern __shared__ float sm[];
    float* bs = sm;                      // [2][256][33]
    float* wzs = sm + 2 * 256 * 33;      // [128][16]

    const int tid = threadIdx.x;
    const int jg = tid & 31;
    const int hg = (tid >> 5) & 3;
    const int ig = tid >> 7;
    const int i0 = blockIdx.x * 2;
    const int j0 = blockIdx.y * 256;

    for (int t = tid; t < CZ * NH; t += 256) wzs[t] = Wz[t];

    float acc[8][4];
#pragma unroll
    for (int kk = 0; kk < 8; kk++)
#pragma unroll
        for (int hh = 0; hh < 4; hh++) acc[kk][hh] = 0.f;

    for (int cc = 0; cc < CZ; cc += 32) {
        __syncthreads();
        // load 2 x 256 x 32 floats = 4096 float4, 16 per thread
#pragma unroll
        for (int p = 0; p < 16; p++) {
            int slot = tid + 256 * p;
            int c4 = slot & 7;
            int row = slot >> 3;          // 0..511
            int ii = row >> 8;
            int j = row & 255;
            float4 vv = *(const float4*)(bias +
                ((size_t)(i0 + ii) * NJ + (j0 + j)) * CZ + cc + c4 * 4);
            float* dst = bs + ((size_t)ii * 256 + j) * 33 + c4 * 4;
            dst[0] = vv.x; dst[1] = vv.y; dst[2] = vv.z; dst[3] = vv.w;
        }
        __syncthreads();

#pragma unroll
        for (int c = 0; c < 32; c++) {
            const float* wrow = wzs + (cc + c) * NH + hg * 4;
            float w0 = wrow[0], w1 = wrow[1], w2 = wrow[2], w3 = wrow[3];
#pragma unroll
            for (int kk = 0; kk < 8; kk++) {
                float bv = bs[((size_t)ig * 256 + (jg + 32 * kk)) * 33 + c];
                acc[kk][0] += bv * w0;
                acc[kk][1] += bv * w1;
                acc[kk][2] += bv * w2;
                acc[kk][3] += bv * w3;
            }
        }
    }

    const int i = i0 + ig;
#pragma unroll
    for (int hh = 0; hh < 4; hh++) {
        int h = hg * 4 + hh;
        size_t base = ((size_t)h * NI + i) * NJ;
#pragma unroll
        for (int kk = 0; kk < 8; kk++) {
            int j = j0 + jg + 32 * kk;
            z[base + j] = acc[kk][hh] + (1.f - mask[j]) * (-1000000.0f);
        }
    }
}

// ---------------- attention: per (head, 64-i tile), stream j in 64-chunks ------------
// online softmax; P reuses K's smem buffer. Thread: 4i x 4j scores, 4i x 4d output.
#define AT_SMEM ((64 * 64 + 64 * 65 + 64 * 64) * 4)
__global__ __launch_bounds__(256) void attn_kernel(
    const float* __restrict__ q, const float* __restrict__ k,
    const float* __restrict__ v, const float* __restrict__ z,
    float* __restrict__ o)
{
    extern __shared__ float sm[];
    float* qs = sm;                       // [64][64]
    float* ks = sm + 64 * 64;             // [64][65], reused as P[64 i][65]
    float* vs = sm + 64 * 64 + 64 * 65;   // [64][64]

    const int h = blockIdx.x;
    const int i0 = blockIdx.y * 64;
    const int tid = threadIdx.x;
    const int tx = tid & 15;
    const int ty = tid >> 4;

    // load Q tile (64 x 64)
#pragma unroll
    for (int p = 0; p < 4; p++) {
        int slot = tid + 256 * p;
        int ii = slot >> 4;
        int d4 = slot & 15;
        float4 vv = *(const float4*)(q + (size_t)(i0 + ii) * CS + h * HD + d4 * 4);
        float* dst = qs + ii * 64 + d4 * 4;
        dst[0] = vv.x; dst[1] = vv.y; dst[2] = vv.z; dst[3] = vv.w;
    }

    float mrow[4], lrow[4], O[4][4];
#pragma unroll
    for (int r = 0; r < 4; r++) {
        mrow[r] = -3.0e38f;
        lrow[r] = 0.f;
#pragma unroll
        for (int c = 0; c < 4; c++) O[r][c] = 0.f;
    }

    for (int j0 = 0; j0 < NJ; j0 += 64) {
        __syncthreads();  // previous PV done reading ks(P)/vs
        // load K,V tiles (64 x 64 each)
#pragma unroll
        for (int p = 0; p < 4; p++) {
            int slot = tid + 256 * p;
            int jj = slot >> 4;
            int d4 = slot & 15;
            float4 kv = *(const float4*)(k + (size_t)(j0 + jj) * CS + h * HD + d4 * 4);
            float* kd = ks + jj * 65 + d4 * 4;
            kd[0] = kv.x; kd[1] = kv.y; kd[2] = kv.z; kd[3] = kv.w;
            float4 vv = *(const float4*)(v + (size_t)(j0 + jj) * CS + h * HD + d4 * 4);
            float* vd = vs + jj * 64 + d4 * 4;
            vd[0] = vv.x; vd[1] = vv.y; vd[2] = vv.z; vd[3] = vv.w;
        }
        __syncthreads();

        float S[4][4];
#pragma unroll
        for (int r = 0; r < 4; r++)
#pragma unroll
            for (int c = 0; c < 4; c++) S[r][c] = 0.f;

#pragma unroll
        for (int d = 0; d < 64; d++) {
            float a[4], b[4];
#pragma unroll
            for (int r = 0; r < 4; r++) a[r] = qs[(ty + 16 * r) * 64 + d];
#pragma unroll
            for (int c = 0; c < 4; c++) b[c] = ks[(tx + 16 * c) * 65 + d];
#pragma unroll
            for (int r = 0; r < 4; r++)
#pragma unroll
                for (int c = 0; c < 4; c++) S[r][c] += a[r] * b[c];
        }

        // scale + pair bias
#pragma unroll
        for (int r = 0; r < 4; r++) {
            size_t zb = ((size_t)h * NI + (i0 + ty + 16 * r)) * NJ + j0;
#pragma unroll
            for (int c = 0; c < 4; c++)
                S[r][c] = S[r][c] * 0.125f + z[zb + tx + 16 * c];
        }

        // online softmax update
#pragma unroll
        for (int r = 0; r < 4; r++) {
            float mc = S[r][0];
#pragma unroll
            for (int c = 1; c < 4; c++) mc = fmaxf(mc, S[r][c]);
#pragma unroll
            for (int off = 1; off < 16; off <<= 1)
                mc = fmaxf(mc, __shfl_xor_sync(0xffffffffu, mc, off));
            float mnew = fmaxf(mrow[r], mc);
            float sc = __expf(mrow[r] - mnew);
            mrow[r] = mnew;
            lrow[r] *= sc;
#pragma unroll
            for (int c = 0; c < 4; c++) O[r][c] *= sc;
            float rs = 0.f;
#pragma unroll
            for (int c = 0; c < 4; c++) {
                S[r][c] = __expf(S[r][c] - mnew);
                rs += S[r][c];
            }
#pragma unroll
            for (int off = 1; off < 16; off <<= 1)
                rs += __shfl_xor_sync(0xffffffffu, rs, off);
            lrow[r] += rs;
        }

        __syncthreads();  // all threads done reading ks before overwrite as P
#pragma unroll
        for (int r = 0; r < 4; r++)
#pragma unroll
            for (int c = 0; c < 4; c++)
                ks[(ty + 16 * r) * 65 + (tx + 16 * c)] = S[r][c];
        __syncthreads();

        // O += P @ V   (d index = tx + 16c)
#pragma unroll
        for (int j = 0; j < 64; j++) {
            float a[4], b[4];
#pragma unroll
            for (int r = 0; r < 4; r++) a[r] = ks[(ty + 16 * r) * 65 + j];
#pragma unroll
            for (int c = 0; c < 4; c++) b[c] = vs[j * 64 + tx + 16 * c];
#pragma unroll
            for (int r = 0; r < 4; r++)
#pragma unroll
                for (int c = 0; c < 4; c++) O[r][c] += a[r] * b[c];
        }
    }

#pragma unroll
    for (int r = 0; r < 4; r++) {
        float inv = 1.f / lrow[r];
        size_t ob = (size_t)(i0 + ty + 16 * r) * CS + h * HD;
#pragma unroll
        for (int c = 0; c < 4; c++)
            o[ob + tx + 16 * c] = O[r][c] * inv;
    }
}

// ---------------- launch ----------------
extern "C" void kernel_launch(void* const* d_in, const int* in_sizes, int n_in,
                              void* d_out, int out_size)
{
    const float* s    = (const float*)d_in[0];
    const float* kin  = (const float*)d_in[1];
    const float* mask = (const float*)d_in[2];
    const float* bias = (const float*)d_in[3];
    const float* Wq   = (const float*)d_in[4];
    const float* bq   = (const float*)d_in[5];
    const float* Wk   = (const float*)d_in[6];
    const float* Wv   = (const float*)d_in[7];
    const float* Wg   = (const float*)d_in[8];
    const float* Wo   = (const float*)d_in[9];
    const float* Wz   = (const float*)d_in[10];
    float* out = (float*)d_out;

    float *q, *k, *v, *g, *o, *z;
    cudaGetSymbolAddress((void**)&q, g_q);
    cudaGetSymbolAddress((void**)&k, g_k);
    cudaGetSymbolAddress((void**)&v, g_v);
    cudaGetSymbolAddress((void**)&g, g_g);
    cudaGetSymbolAddress((void**)&o, g_o);
    cudaGetSymbolAddress((void**)&z, g_z);

    dim3 ggrid(CS / 64, NI / 128);
    gemm_xwT<1, false><<<ggrid, 256>>>(s,   nullptr, Wq, bq,      q);
    gemm_xwT<0, false><<<ggrid, 256>>>(kin, nullptr, Wk, nullptr, k);
    gemm_xwT<0, false><<<ggrid, 256>>>(kin, nullptr, Wv, nullptr, v);
    gemm_xwT<2, false><<<ggrid, 256>>>(s,   nullptr, Wg, nullptr, g);

    cudaFuncSetAttribute(zbias_kernel, cudaFuncAttributeMaxDynamicSharedMemorySize, ZB_SMEM);
    zbias_kernel<<<dim3(NI / 2, NJ / 256), 256, ZB_SMEM>>>(bias, Wz, mask, z);

    cudaFuncSetAttribute(attn_kernel, cudaFuncAttributeMaxDynamicSharedMemorySize, AT_SMEM);
    attn_kernel<<<dim3(NH, NI / 64), 256, AT_SMEM>>>(q, k, v, z, o);

    gemm_xwT<0, true><<<ggrid, 256>>>(g, o, Wo, nullptr, out);
}

// round 5
// speedup vs baseline: 1.4017x; 1.4017x over previous
#include <cuda_runtime.h>
#include <math.h>

#define CS 1024
#define CZ 128
#define NH 16
#define HD 64
#define NI 1024
#define NJ 1024

// ---------------- scratch (device globals; no allocation allowed) ----------------
__device__ float g_q[NI * CS];
__device__ float g_k[NJ * CS];
__device__ float g_v[NJ * CS];
__device__ float g_g[NI * CS];
__device__ float g_o[NI * CS];
__device__ float g_z[(size_t)NH * NI * NJ];   // 64 MB

// =====================================================================
// Generic SIMT GEMM core: C[m][n] = act( sum_k A[m][k]*W[n][k] (+b[n]) )
// BM x BN x 16 tiles, 256 threads, TM x TN microtile, all-vector LDS.
// mode: 0 plain, 1 +bias, 2 sigmoid. MUL: A *= A2 at load (g (*) o).
// Requires BN/TN == 16 and BM/TM == 16 (256 threads).
// =====================================================================
template <int BM, int BN, int TM, int TN, bool MUL>
__device__ __forceinline__ void gemm_core(
    const float* __restrict__ A, const float* __restrict__ A2,
    const float* __restrict__ W, const float* __restrict__ bvec,
    float* __restrict__ C, int mode, int m0, int n0)
{
    constexpr int AV = TM / 4;   // float4 frags per a
    constexpr int BV = TN / 4;
    const int K = CS, N = CS;

    __shared__ __align__(16) float As[16][BM + 4];
    __shared__ __align__(16) float Bs[16][BN + 4];

    const int tid = threadIdx.x;
    const int tx = tid & 15;     // BN/TN == 16
    const int ty = tid >> 4;     // BM/TM == 16

    float acc[TM][TN];
#pragma unroll
    for (int r = 0; r < TM; r++)
#pragma unroll
        for (int c = 0; c < TN; c++) acc[r][c] = 0.f;

    for (int k0 = 0; k0 < K; k0 += 16) {
        // A tile: BM x 16 floats = BM*4 float4 -> BM/64 per thread
#pragma unroll
        for (int p = 0; p < BM / 64; p++) {
            int slot = tid + 256 * p;
            int m = slot >> 2;
            int k4 = slot & 3;
            float4 av = *(const float4*)(A + (size_t)(m0 + m) * K + k0 + k4 * 4);
            if (MUL) {
                float4 a2 = *(const float4*)(A2 + (size_t)(m0 + m) * K + k0 + k4 * 4);
                av.x *= a2.x; av.y *= a2.y; av.z *= a2.z; av.w *= a2.w;
            }
            As[k4 * 4 + 0][m] = av.x;
            As[k4 * 4 + 1][m] = av.y;
            As[k4 * 4 + 2][m] = av.z;
            As[k4 * 4 + 3][m] = av.w;
        }
        // B tile: BN x 16 floats
#pragma unroll
        for (int p = 0; p < BN / 64; p++) {
            int slot = tid + 256 * p;
            int n = slot >> 2;
            int k4 = slot & 3;
            float4 bv = *(const float4*)(W + (size_t)(n0 + n) * K + k0 + k4 * 4);
            Bs[k4 * 4 + 0][n] = bv.x;
            Bs[k4 * 4 + 1][n] = bv.y;
            Bs[k4 * 4 + 2][n] = bv.z;
            Bs[k4 * 4 + 3][n] = bv.w;
        }
        __syncthreads();

#pragma unroll
        for (int k = 0; k < 16; k++) {
            float a[TM], b[TN];
#pragma unroll
            for (int u = 0; u < AV; u++) {
                float4 t = *(const float4*)&As[k][ty * 4 + u * (BM / AV)];
                a[4 * u + 0] = t.x; a[4 * u + 1] = t.y;
                a[4 * u + 2] = t.z; a[4 * u + 3] = t.w;
            }
#pragma unroll
            for (int v = 0; v < BV; v++) {
                float4 t = *(const float4*)&Bs[k][tx * 4 + v * (BN / BV)];
                b[4 * v + 0] = t.x; b[4 * v + 1] = t.y;
                b[4 * v + 2] = t.z; b[4 * v + 3] = t.w;
            }
#pragma unroll
            for (int r = 0; r < TM; r++)
#pragma unroll
                for (int c = 0; c < TN; c++) acc[r][c] += a[r] * b[c];
        }
        __syncthreads();
    }

    // epilogue: vectorized float4 stores
#pragma unroll
    for (int u = 0; u < AV; u++) {
#pragma unroll
        for (int l = 0; l < 4; l++) {
            int m = m0 + ty * 4 + u * (BM / AV) + l;
#pragma unroll
            for (int v = 0; v < BV; v++) {
                int n = n0 + tx * 4 + v * (BN / BV);
                float4 res;
                float* src = &acc[4 * u + l][4 * v];
                res.x = src[0]; res.y = src[1]; res.z = src[2]; res.w = src[3];
                if (mode == 1) {
                    res.x += bvec[n + 0]; res.y += bvec[n + 1];
                    res.z += bvec[n + 2]; res.w += bvec[n + 3];
                } else if (mode == 2) {
                    res.x = 1.f / (1.f + __expf(-res.x));
                    res.y = 1.f / (1.f + __expf(-res.y));
                    res.z = 1.f / (1.f + __expf(-res.z));
                    res.w = 1.f / (1.f + __expf(-res.w));
                }
                *(float4*)(C + (size_t)m * N + n) = res;
            }
        }
    }
}

// Fused 4 projections: z = 0:q(+bq), 1:k, 2:v, 3:g(sigmoid)
__global__ __launch_bounds__(256) void gemm_fused4(
    const float* __restrict__ s, const float* __restrict__ kin,
    const float* __restrict__ Wq, const float* __restrict__ bq,
    const float* __restrict__ Wk, const float* __restrict__ Wv,
    const float* __restrict__ Wg,
    float* __restrict__ q, float* __restrict__ k,
    float* __restrict__ v, float* __restrict__ g)
{
    const float* A; const float* W; float* C;
    const float* bvec = nullptr; int mode = 0;
    switch (blockIdx.z) {
        case 0: A = s;   W = Wq; C = q; bvec = bq; mode = 1; break;
        case 1: A = kin; W = Wk; C = k; break;
        case 2: A = kin; W = Wv; C = v; break;
        default: A = s;  W = Wg; C = g; mode = 2; break;
    }
    gemm_core<128, 128, 8, 8, false>(A, nullptr, W, bvec, C, mode,
                                     blockIdx.y * 128, blockIdx.x * 128);
}

// Final GEMM: out = (g (*) o) @ Wo^T   (64x64 tiles -> 256 blocks)
__global__ __launch_bounds__(256) void gemm_out(
    const float* __restrict__ g, const float* __restrict__ o,
    const float* __restrict__ Wo, float* __restrict__ out)
{
    gemm_core<64, 64, 4, 4, true>(g, o, Wo, nullptr, out, 0,
                                  blockIdx.y * 64, blockIdx.x * 64);
}

// ---------------- z kernel: z[h,i,j] = sum_c bias[i,j,c]*Wz[c,h] + (1-mask[j])*(-1e6)
#define ZB_SMEM ((2 * 256 * 33 + CZ * NH) * 4)
__global__ __launch_bounds__(256) void zbias_kernel(
    const float* __restrict__ bias, const float* __restrict__ Wz,
    const float* __restrict__ mask, float* __restrict__ z)
{
    extern __shared__ float sm[];
    float* bs = sm;                      // [2][256][33]
    float* wzs = sm + 2 * 256 * 33;      // [128][16]

    const int tid = threadIdx.x;
    const int jg = tid & 31;
    const int hg = (tid >> 5) & 3;
    const int ig = tid >> 7;
    const int i0 = blockIdx.x * 2;
    const int j0 = blockIdx.y * 256;

    for (int t = tid; t < CZ * NH; t += 256) wzs[t] = Wz[t];

    float acc[8][4];
#pragma unroll
    for (int kk = 0; kk < 8; kk++)
#pragma unroll
        for (int hh = 0; hh < 4; hh++) acc[kk][hh] = 0.f;

    for (int cc = 0; cc < CZ; cc += 32) {
        __syncthreads();
#pragma unroll
        for (int p = 0; p < 16; p++) {
            int slot = tid + 256 * p;
            int c4 = slot & 7;
            int row = slot >> 3;          // 0..511
            int ii = row >> 8;
            int j = row & 255;
            float4 vv = *(const float4*)(bias +
                ((size_t)(i0 + ii) * NJ + (j0 + j)) * CZ + cc + c4 * 4);
            float* dst = bs + ((size_t)ii * 256 + j) * 33 + c4 * 4;
            dst[0] = vv.x; dst[1] = vv.y; dst[2] = vv.z; dst[3] = vv.w;
        }
        __syncthreads();

#pragma unroll
        for (int c = 0; c < 32; c++) {
            const float* wrow = wzs + (cc + c) * NH + hg * 4;
            float w0 = wrow[0], w1 = wrow[1], w2 = wrow[2], w3 = wrow[3];
#pragma unroll
            for (int kk = 0; kk < 8; kk++) {
                float bv = bs[((size_t)ig * 256 + (jg + 32 * kk)) * 33 + c];
                acc[kk][0] += bv * w0;
                acc[kk][1] += bv * w1;
                acc[kk][2] += bv * w2;
                acc[kk][3] += bv * w3;
            }
        }
    }

    const int i = i0 + ig;
#pragma unroll
    for (int hh = 0; hh < 4; hh++) {
        int h = hg * 4 + hh;
        size_t base = ((size_t)h * NI + i) * NJ;
#pragma unroll
        for (int kk = 0; kk < 8; kk++) {
            int j = j0 + jg + 32 * kk;
            z[base + j] = acc[kk][hh] + (1.f - mask[j]) * (-1000000.0f);
        }
    }
}

// ---------------- attention: per (head, 64-i tile), stream j in 64-chunks ------------
// Vectorized: QK over d (float4 from qs/ks), PV over j (P rows + V transposed).
// smem: qs[64][68], ks[64][68] (reused as P), vsT[64][68]
#define AT_PAD 68
#define AT_SMEM (3 * 64 * AT_PAD * 4)
__global__ __launch_bounds__(256) void attn_kernel(
    const float* __restrict__ q, const float* __restrict__ k,
    const float* __restrict__ v, const float* __restrict__ z,
    float* __restrict__ o)
{
    extern __shared__ __align__(16) float sm[];
    float* qs  = sm;                        // [64][68] q[i][d]
    float* ks  = sm + 64 * AT_PAD;          // [64][68] k[j][d], reused as P[i][j]
    float* vsT = sm + 2 * 64 * AT_PAD;      // [64][68] v^T[d][j]

    const int h = blockIdx.x;
    const int i0 = blockIdx.y * 64;
    const int tid = threadIdx.x;
    const int tx = tid & 15;
    const int ty = tid >> 4;

    // load Q tile (64 x 64)
#pragma unroll
    for (int p = 0; p < 4; p++) {
        int slot = tid + 256 * p;
        int ii = slot >> 4;
        int d4 = slot & 15;
        float4 vv = *(const float4*)(q + (size_t)(i0 + ii) * CS + h * HD + d4 * 4);
        float* dst = qs + ii * AT_PAD + d4 * 4;
        dst[0] = vv.x; dst[1] = vv.y; dst[2] = vv.z; dst[3] = vv.w;
    }

    float mrow[4], lrow[4], O[4][4];
#pragma unroll
    for (int r = 0; r < 4; r++) {
        mrow[r] = -3.0e38f;
        lrow[r] = 0.f;
#pragma unroll
        for (int c = 0; c < 4; c++) O[r][c] = 0.f;
    }

    for (int j0 = 0; j0 < NJ; j0 += 64) {
        __syncthreads();  // previous PV done reading ks(P)/vsT
        // load K tile row-major, V tile transposed
#pragma unroll
        for (int p = 0; p < 4; p++) {
            int slot = tid + 256 * p;
            int jj = slot >> 4;
            int d4 = slot & 15;
            float4 kv = *(const float4*)(k + (size_t)(j0 + jj) * CS + h * HD + d4 * 4);
            float* kd = ks + jj * AT_PAD + d4 * 4;
            kd[0] = kv.x; kd[1] = kv.y; kd[2] = kv.z; kd[3] = kv.w;
            float4 vv = *(const float4*)(v + (size_t)(j0 + jj) * CS + h * HD + d4 * 4);
            vsT[(d4 * 4 + 0) * AT_PAD + jj] = vv.x;
            vsT[(d4 * 4 + 1) * AT_PAD + jj] = vv.y;
            vsT[(d4 * 4 + 2) * AT_PAD + jj] = vv.z;
            vsT[(d4 * 4 + 3) * AT_PAD + jj] = vv.w;
        }
        __syncthreads();

        float S[4][4];
#pragma unroll
        for (int r = 0; r < 4; r++)
#pragma unroll
            for (int c = 0; c < 4; c++) S[r][c] = 0.f;

        // S += Q K^T, vectorized over d
#pragma unroll
        for (int d0 = 0; d0 < 64; d0 += 4) {
            float4 a4[4], b4[4];
#pragma unroll
            for (int r = 0; r < 4; r++)
                a4[r] = *(const float4*)&qs[(ty + 16 * r) * AT_PAD + d0];
#pragma unroll
            for (int c = 0; c < 4; c++)
                b4[c] = *(const float4*)&ks[(tx + 16 * c) * AT_PAD + d0];
#pragma unroll
            for (int r = 0; r < 4; r++)
#pragma unroll
                for (int c = 0; c < 4; c++) {
                    S[r][c] += a4[r].x * b4[c].x;
                    S[r][c] += a4[r].y * b4[c].y;
                    S[r][c] += a4[r].z * b4[c].z;
                    S[r][c] += a4[r].w * b4[c].w;
                }
        }

        // scale + pair bias
#pragma unroll
        for (int r = 0; r < 4; r++) {
            size_t zb = ((size_t)h * NI + (i0 + ty + 16 * r)) * NJ + j0;
#pragma unroll
            for (int c = 0; c < 4; c++)
                S[r][c] = S[r][c] * 0.125f + z[zb + tx + 16 * c];
        }

        // online softmax update
#pragma unroll
        for (int r = 0; r < 4; r++) {
            float mc = S[r][0];
#pragma unroll
            for (int c = 1; c < 4; c++) mc = fmaxf(mc, S[r][c]);
#pragma unroll
            for (int off = 1; off < 16; off <<= 1)
                mc = fmaxf(mc, __shfl_xor_sync(0xffffffffu, mc, off));
            float mnew = fmaxf(mrow[r], mc);
            float sc = __expf(mrow[r] - mnew);
            mrow[r] = mnew;
            lrow[r] *= sc;
#pragma unroll
            for (int c = 0; c < 4; c++) O[r][c] *= sc;
            float rs = 0.f;
#pragma unroll
            for (int c = 0; c < 4; c++) {
                S[r][c] = __expf(S[r][c] - mnew);
                rs += S[r][c];
            }
#pragma unroll
            for (int off = 1; off < 16; off <<= 1)
                rs += __shfl_xor_sync(0xffffffffu, rs, off);
            lrow[r] += rs;
        }

        __syncthreads();  // all threads done reading ks before overwrite as P
#pragma unroll
        for (int r = 0; r < 4; r++)
#pragma unroll
            for (int c = 0; c < 4; c++)
                ks[(ty + 16 * r) * AT_PAD + (tx + 16 * c)] = S[r][c];
        __syncthreads();

        // O += P @ V, vectorized over j (P rows x vsT rows)
#pragma unroll
        for (int jq = 0; jq < 64; jq += 4) {
            float4 a4[4], b4[4];
#pragma unroll
            for (int r = 0; r < 4; r++)
                a4[r] = *(const float4*)&ks[(ty + 16 * r) * AT_PAD + jq];
#pragma unroll
            for (int c = 0; c < 4; c++)
                b4[c] = *(const float4*)&vsT[(tx + 16 * c) * AT_PAD + jq];
#pragma unroll
            for (int r = 0; r < 4; r++)
#pragma unroll
                for (int c = 0; c < 4; c++) {
                    O[r][c] += a4[r].x * b4[c].x;
                    O[r][c] += a4[r].y * b4[c].y;
                    O[r][c] += a4[r].z * b4[c].z;
                    O[r][c] += a4[r].w * b4[c].w;
                }
        }
    }

#pragma unroll
    for (int r = 0; r < 4; r++) {
        float inv = 1.f / lrow[r];
        size_t ob = (size_t)(i0 + ty + 16 * r) * CS + h * HD;
#pragma unroll
        for (int c = 0; c < 4; c++)
            o[ob + tx + 16 * c] = O[r][c] * inv;
    }
}

// ---------------- launch ----------------
extern "C" void kernel_launch(void* const* d_in, const int* in_sizes, int n_in,
                              void* d_out, int out_size)
{
    const float* s    = (const float*)d_in[0];
    const float* kin  = (const float*)d_in[1];
    const float* mask = (const float*)d_in[2];
    const float* bias = (const float*)d_in[3];
    const float* Wq   = (const float*)d_in[4];
    const float* bq   = (const float*)d_in[5];
    const float* Wk   = (const float*)d_in[6];
    const float* Wv   = (const float*)d_in[7];
    const float* Wg   = (const float*)d_in[8];
    const float* Wo   = (const float*)d_in[9];
    const float* Wz   = (const float*)d_in[10];
    float* out = (float*)d_out;

    float *q, *k, *v, *g, *o, *z;
    cudaGetSymbolAddress((void**)&q, g_q);
    cudaGetSymbolAddress((void**)&k, g_k);
    cudaGetSymbolAddress((void**)&v, g_v);
    cudaGetSymbolAddress((void**)&g, g_g);
    cudaGetSymbolAddress((void**)&o, g_o);
    cudaGetSymbolAddress((void**)&z, g_z);

    // 4 projections fused in one launch: 8x8x4 = 256 blocks
    gemm_fused4<<<dim3(8, 8, 4), 256>>>(s, kin, Wq, bq, Wk, Wv, Wg, q, k, v, g);

    cudaFuncSetAttribute(zbias_kernel, cudaFuncAttributeMaxDynamicSharedMemorySize, ZB_SMEM);
    zbias_kernel<<<dim3(NI / 2, NJ / 256), 256, ZB_SMEM>>>(bias, Wz, mask, z);

    cudaFuncSetAttribute(attn_kernel, cudaFuncAttributeMaxDynamicSharedMemorySize, AT_SMEM);
    attn_kernel<<<dim3(NH, NI / 64), 256, AT_SMEM>>>(q, k, v, z, o);

    gemm_out<<<dim3(16, 16), 256>>>(g, o, Wo, out);
}

// round 8
// speedup vs baseline: 1.9336x; 1.3795x over previous
#include <cuda_runtime.h>
#include <cuda_bf16.h>
#include <math.h>
#include <stdint.h>

#define CS 1024
#define CZ 128
#define NH 16
#define HD 64
#define NI 1024
#define NJ 1024
#define NELEM (NI * CS)

// ---------------- scratch (device globals; no allocation allowed) ----------------
__device__ float g_q[NELEM];
__device__ float g_k[NELEM];
__device__ float g_v[NELEM];
__device__ float g_g[NELEM];
__device__ float g_o[NELEM];
__device__ float g_z[(size_t)NH * NI * NJ];   // 64 MB

// bf16 hi/lo split buffers
__device__ __nv_bfloat16 g_sh[NELEM],  g_sl[NELEM];     // s
__device__ __nv_bfloat16 g_kh[NELEM],  g_kl[NELEM];     // k_in
__device__ __nv_bfloat16 g_wqh[NELEM], g_wql[NELEM];
__device__ __nv_bfloat16 g_wkh[NELEM], g_wkl[NELEM];
__device__ __nv_bfloat16 g_wvh[NELEM], g_wvl[NELEM];
__device__ __nv_bfloat16 g_wgh[NELEM], g_wgl[NELEM];
__device__ __nv_bfloat16 g_woh[NELEM], g_wol[NELEM];
__device__ __nv_bfloat16 g_goh[NELEM], g_gol[NELEM];    // g (*) o

// =====================================================================
// helpers (baseline PTX only — NO tcgen05 on this toolchain path)
// =====================================================================
__device__ __forceinline__ uint32_t smem_u32(const void* p) {
    uint32_t a;
    asm("{ .reg .u64 t; cvta.to.shared.u64 t, %1; cvt.u32.u64 %0, t; }"
        : "=r"(a) : "l"(p));
    return a;
}

__device__ __forceinline__ void cp16(uint32_t dst, const void* src) {
    uint64_t g;
    asm("cvta.to.global.u64 %0, %1;" : "=l"(g) : "l"(src));
    asm volatile("cp.async.cg.shared.global [%0], [%1], 16;" :: "r"(dst), "l"(g));
}

__device__ __forceinline__ void ldm_x4(uint32_t* r, uint32_t addr) {
    asm volatile("ldmatrix.sync.aligned.m8n8.x4.shared.b16 {%0,%1,%2,%3}, [%4];"
        : "=r"(r[0]), "=r"(r[1]), "=r"(r[2]), "=r"(r[3]) : "r"(addr));
}

__device__ __forceinline__ void mma16816(float* d, const uint32_t* a, const uint32_t* b) {
    asm volatile(
        "mma.sync.aligned.m16n8k16.row.col.f32.bf16.bf16.f32 "
        "{%0,%1,%2,%3}, {%4,%5,%6,%7}, {%8,%9}, {%0,%1,%2,%3};"
        : "+f"(d[0]), "+f"(d[1]), "+f"(d[2]), "+f"(d[3])
        : "r"(a[0]), "r"(a[1]), "r"(a[2]), "r"(a[3]), "r"(b[0]), "r"(b[1]));
}

__device__ __forceinline__ uint32_t swz(uint32_t off) {
    return off ^ ((off >> 3) & 0x70);
}

// =====================================================================
// split conversion kernels: x -> (hi=bf16(x), lo=bf16(x-hi))
// =====================================================================
struct SplitArgs {
    const float* src[7];
    __nv_bfloat16* hi[7];
    __nv_bfloat16* lo[7];
};

__device__ __forceinline__ void split4(float4 v, __nv_bfloat162* hi2,
                                       __nv_bfloat162* lo2, size_t i) {
    __nv_bfloat16 h0 = __float2bfloat16(v.x);
    __nv_bfloat16 h1 = __float2bfloat16(v.y);
    __nv_bfloat16 h2 = __float2bfloat16(v.z);
    __nv_bfloat16 h3 = __float2bfloat16(v.w);
    __nv_bfloat16 l0 = __float2bfloat16(v.x - __bfloat162float(h0));
    __nv_bfloat16 l1 = __float2bfloat16(v.y - __bfloat162float(h1));
    __nv_bfloat16 l2 = __float2bfloat16(v.z - __bfloat162float(h2));
    __nv_bfloat16 l3 = __float2bfloat16(v.w - __bfloat162float(h3));
    __nv_bfloat162 ph0; ph0.x = h0; ph0.y = h1;
    __nv_bfloat162 ph1; ph1.x = h2; ph1.y = h3;
    __nv_bfloat162 pl0; pl0.x = l0; pl0.y = l1;
    __nv_bfloat162 pl1; pl1.x = l2; pl1.y = l3;
    hi2[2 * i] = ph0; hi2[2 * i + 1] = ph1;
    lo2[2 * i] = pl0; lo2[2 * i + 1] = pl1;
}

__global__ __launch_bounds__(256) void split7(SplitArgs a) {
    const float4* src = (const float4*)a.src[blockIdx.y];
    __nv_bfloat162* hi2 = (__nv_bfloat162*)a.hi[blockIdx.y];
    __nv_bfloat162* lo2 = (__nv_bfloat162*)a.lo[blockIdx.y];
    int t = blockIdx.x * 256 + threadIdx.x;
    for (size_t i = t; i < NELEM / 4; i += 256 * 256)
        split4(src[i], hi2, lo2, i);
}

__global__ __launch_bounds__(256) void mulsplit(
    const float* __restrict__ g, const float* __restrict__ o,
    __nv_bfloat16* hi, __nv_bfloat16* lo)
{
    const float4* g4 = (const float4*)g;
    const float4* o4 = (const float4*)o;
    __nv_bfloat162* hi2 = (__nv_bfloat162*)hi;
    __nv_bfloat162* lo2 = (__nv_bfloat162*)lo;
    int t = blockIdx.x * 256 + threadIdx.x;
    for (size_t i = t; i < NELEM / 4; i += 256 * 256) {
        float4 gv = g4[i], ov = o4[i];
        float4 v;
        v.x = gv.x * ov.x; v.y = gv.y * ov.y;
        v.z = gv.z * ov.z; v.w = gv.w * ov.w;
        split4(v, hi2, lo2, i);
    }
}

// =====================================================================
// bf16-split GEMM via mma.sync: C[m][n] = act( sum_k A[m][k]*W[n][k] (+b[n]) )
// 128x128 CTA tile, BK=64 bf16 (128B rows, SW128 swizzle), 3-stage cp.async,
// 8 warps as 4(M) x 2(N) -> 32x64 warp tiles; 3 MMA terms (hh, lh, hl).
// MODE: 0 plain, 1 +bias, 2 sigmoid
// =====================================================================
#define STAGE_BYTES 65536
#define GEMM_SMEM (3 * STAGE_BYTES + 1024)

__device__ __forceinline__ void load_stage(
    uint32_t sbase, int s, int tid,
    const __nv_bfloat16* Ah, const __nv_bfloat16* Al,
    const __nv_bfloat16* Bh, const __nv_bfloat16* Bl,
    int m0, int n0)
{
    uint32_t sb = sbase + (uint32_t)(s % 3) * STAGE_BYTES;
    int k0 = s * 64;
#pragma unroll
    for (int p = 0; p < 4; p++) {
        int slot = tid + 256 * p;
        int row = slot >> 3;
        int ch = slot & 7;
        uint32_t off = swz((uint32_t)(row * 128 + ch * 16));
        size_t aoff = (size_t)(m0 + row) * CS + k0 + ch * 8;
        size_t boff = (size_t)(n0 + row) * CS + k0 + ch * 8;
        cp16(sb + off,          Ah + aoff);
        cp16(sb + 16384u + off, Al + aoff);
        cp16(sb + 32768u + off, Bh + boff);
        cp16(sb + 49152u + off, Bl + boff);
    }
}

template <int MODE>
__device__ void gemm_mma_core(
    const __nv_bfloat16* Ah, const __nv_bfloat16* Al,
    const __nv_bfloat16* Bh, const __nv_bfloat16* Bl,
    const float* bvec, float* C, int m0, int n0)
{
    extern __shared__ __align__(16) char dsm[];
    const int tid = threadIdx.x;
    uint32_t sbase = smem_u32(dsm);
    sbase = (sbase + 1023u) & ~1023u;

    const int w  = tid >> 5;
    const int ln = tid & 31;
    const int wm = w & 3;        // 4 warps over M: 32 rows each
    const int wn = w >> 2;       // 2 warps over N: 64 cols each

    float acc[2][8][4];
#pragma unroll
    for (int mt = 0; mt < 2; mt++)
#pragma unroll
        for (int nt = 0; nt < 8; nt++)
#pragma unroll
            for (int e = 0; e < 4; e++) acc[mt][nt][e] = 0.f;

    // prefetch stages 0,1
    load_stage(sbase, 0, tid, Ah, Al, Bh, Bl, m0, n0);
    asm volatile("cp.async.commit_group;" ::: "memory");
    load_stage(sbase, 1, tid, Ah, Al, Bh, Bl, m0, n0);
    asm volatile("cp.async.commit_group;" ::: "memory");

    // ldmatrix lane addressing (within a 128-row x 128B tile):
    //   A x4: row = base + (ln & 15),                 kb = kk*32 + (ln >> 4) * 16
    //   B x4: row = base + (ln & 7) + ((ln>>4)&1)*8,  kb = kk*32 + ((ln>>3)&1) * 16
    const int a_row = wm * 32 + (ln & 15);
    const int a_kb  = (ln >> 4) * 16;
    const int b_row = wn * 64 + (ln & 7) + ((ln >> 4) & 1) * 8;
    const int b_kb  = ((ln >> 3) & 1) * 16;

    for (int s = 0; s < 16; s++) {
        if (s < 15) asm volatile("cp.async.wait_group 1;" ::: "memory");
        else        asm volatile("cp.async.wait_group 0;" ::: "memory");
        __syncthreads();

        uint32_t sb = sbase + (uint32_t)(s % 3) * STAGE_BYTES;
#pragma unroll
        for (int kk = 0; kk < 4; kk++) {
            uint32_t ah[2][4], al[2][4], bh[8][2], bl[8][2];
#pragma unroll
            for (int mt = 0; mt < 2; mt++) {
                uint32_t off = swz((uint32_t)((a_row + mt * 16) * 128 + kk * 32 + a_kb));
                ldm_x4(ah[mt], sb + off);
                ldm_x4(al[mt], sb + 16384u + off);
            }
#pragma unroll
            for (int np = 0; np < 4; np++) {
                uint32_t off = swz((uint32_t)((b_row + np * 16) * 128 + kk * 32 + b_kb));
                uint32_t t4[4];
                ldm_x4(t4, sb + 32768u + off);
                bh[2 * np][0] = t4[0]; bh[2 * np][1] = t4[1];
                bh[2 * np + 1][0] = t4[2]; bh[2 * np + 1][1] = t4[3];
                ldm_x4(t4, sb + 49152u + off);
                bl[2 * np][0] = t4[0]; bl[2 * np][1] = t4[1];
                bl[2 * np + 1][0] = t4[2]; bl[2 * np + 1][1] = t4[3];
            }
#pragma unroll
            for (int mt = 0; mt < 2; mt++)
#pragma unroll
                for (int nt = 0; nt < 8; nt++) {
                    mma16816(acc[mt][nt], ah[mt], bh[nt]);
                    mma16816(acc[mt][nt], al[mt], bh[nt]);
                    mma16816(acc[mt][nt], ah[mt], bl[nt]);
                }
        }

        if (s + 2 < 16) {
            load_stage(sbase, s + 2, tid, Ah, Al, Bh, Bl, m0, n0);
            asm volatile("cp.async.commit_group;" ::: "memory");
        }
    }

    // epilogue: acc[mt][nt] regs {d0,d1} -> (row, n..n+1); {d2,d3} -> (row+8, n..n+1)
    const int er = ln >> 2;          // 0..7
    const int ec = (ln & 3) * 2;     // 0,2,4,6
#pragma unroll
    for (int mt = 0; mt < 2; mt++) {
#pragma unroll
        for (int nt = 0; nt < 8; nt++) {
            int m = m0 + wm * 32 + mt * 16 + er;
            int n = n0 + wn * 64 + nt * 8 + ec;
#pragma unroll
            for (int half = 0; half < 2; half++) {
                float2 r;
                r.x = acc[mt][nt][2 * half + 0];
                r.y = acc[mt][nt][2 * half + 1];
                if (MODE == 1) { r.x += bvec[n]; r.y += bvec[n + 1]; }
                else if (MODE == 2) {
                    r.x = 1.f / (1.f + __expf(-r.x));
                    r.y = 1.f / (1.f + __expf(-r.y));
                }
                *(float2*)(C + (size_t)(m + half * 8) * CS + n) = r;
            }
        }
    }
}

// Fused 4 projections: z = 0:q(+bq), 1:k, 2:v, 3:g(sigmoid)
__global__ __launch_bounds__(256, 1) void gemm_tc4(
    const __nv_bfloat16* sh,  const __nv_bfloat16* sl,
    const __nv_bfloat16* kh,  const __nv_bfloat16* kl,
    const __nv_bfloat16* wqh, const __nv_bfloat16* wql,
    const __nv_bfloat16* wkh, const __nv_bfloat16* wkl,
    const __nv_bfloat16* wvh, const __nv_bfloat16* wvl,
    const __nv_bfloat16* wgh, const __nv_bfloat16* wgl,
    const float* bq,
    float* q, float* k, float* v, float* g)
{
    int m0 = blockIdx.y * 128, n0 = blockIdx.x * 128;
    switch (blockIdx.z) {
        case 0:  gemm_mma_core<1>(sh, sl, wqh, wql, bq,      q, m0, n0); break;
        case 1:  gemm_mma_core<0>(kh, kl, wkh, wkl, nullptr, k, m0, n0); break;
        case 2:  gemm_mma_core<0>(kh, kl, wvh, wvl, nullptr, v, m0, n0); break;
        default: gemm_mma_core<2>(sh, sl, wgh, wgl, nullptr, g, m0, n0); break;
    }
}

__global__ __launch_bounds__(256, 1) void gemm_tc_out(
    const __nv_bfloat16* ah, const __nv_bfloat16* al,
    const __nv_bfloat16* bh, const __nv_bfloat16* bl,
    float* out)
{
    gemm_mma_core<0>(ah, al, bh, bl, nullptr, out,
                     blockIdx.y * 128, blockIdx.x * 128);
}

// ---------------- z kernel: z[h,i,j] = sum_c bias[i,j,c]*Wz[c,h] + (1-mask[j])*(-1e6)
#define ZB_SMEM ((2 * 256 * 33 + CZ * NH) * 4)
__global__ __launch_bounds__(256) void zbias_kernel(
    const float* __restrict__ bias, const float* __restrict__ Wz,
    const float* __restrict__ mask, float* __restrict__ z)
{
    extern __shared__ float sm[];
    float* bs = sm;                      // [2][256][33]
    float* wzs = sm + 2 * 256 * 33;      // [128][16]

    const int tid = threadIdx.x;
    const int jg = tid & 31;
    const int hg = (tid >> 5) & 3;
    const int ig = tid >> 7;
    const int i0 = blockIdx.x * 2;
    const int j0 = blockIdx.y * 256;

    for (int t = tid; t < CZ * NH; t += 256) wzs[t] = Wz[t];

    float acc[8][4];
#pragma unroll
    for (int kk = 0; kk < 8; kk++)
#pragma unroll
        for (int hh = 0; hh < 4; hh++) acc[kk][hh] = 0.f;

    for (int cc = 0; cc < CZ; cc += 32) {
        __syncthreads();
#pragma unroll
        for (int p = 0; p < 16; p++) {
            int slot = tid + 256 * p;
            int c4 = slot & 7;
            int row = slot >> 3;          // 0..511
            int ii = row >> 8;
            int j = row & 255;
            float4 vv = *(const float4*)(bias +
                ((size_t)(i0 + ii) * NJ + (j0 + j)) * CZ + cc + c4 * 4);
            float* dst = bs + ((size_t)ii * 256 + j) * 33 + c4 * 4;
            dst[0] = vv.x; dst[1] = vv.y; dst[2] = vv.z; dst[3] = vv.w;
        }
        __syncthreads();

#pragma unroll
        for (int c = 0; c < 32; c++) {
            const float* wrow = wzs + (cc + c) * NH + hg * 4;
            float w0 = wrow[0], w1 = wrow[1], w2 = wrow[2], w3 = wrow[3];
#pragma unroll
            for (int kk = 0; kk < 8; kk++) {
                float bv = bs[((size_t)ig * 256 + (jg + 32 * kk)) * 33 + c];
                acc[kk][0] += bv * w0;
                acc[kk][1] += bv * w1;
                acc[kk][2] += bv * w2;
                acc[kk][3] += bv * w3;
            }
        }
    }

    const int i = i0 + ig;
#pragma unroll
    for (int hh = 0; hh < 4; hh++) {
        int h = hg * 4 + hh;
        size_t base = ((size_t)h * NI + i) * NJ;
#pragma unroll
        for (int kk = 0; kk < 8; kk++) {
            int j = j0 + jg + 32 * kk;
            z[base + j] = acc[kk][hh] + (1.f - mask[j]) * (-1000000.0f);
        }
    }
}

// ---------------- attention: per (head, 64-i tile), stream j in 64-chunks ------------
#define AT_PAD 68
#define AT_SMEM (3 * 64 * AT_PAD * 4)
__global__ __launch_bounds__(256) void attn_kernel(
    const float* __restrict__ q, const float* __restrict__ k,
    const float* __restrict__ v, const float* __restrict__ z,
    float* __restrict__ o)
{
    extern __shared__ __align__(16) float sm[];
    float* qs  = sm;                        // [64][68] q[i][d]
    float* ks  = sm + 64 * AT_PAD;          // [64][68] k[j][d], reused as P[i][j]
    float* vsT = sm + 2 * 64 * AT_PAD;      // [64][68] v^T[d][j]

    const int h = blockIdx.x;
    const int i0 = blockIdx.y * 64;
    const int tid = threadIdx.x;
    const int tx = tid & 15;
    const int ty = tid >> 4;

#pragma unroll
    for (int p = 0; p < 4; p++) {
        int slot = tid + 256 * p;
        int ii = slot >> 4;
        int d4 = slot & 15;
        float4 vv = *(const float4*)(q + (size_t)(i0 + ii) * CS + h * HD + d4 * 4);
        float* dst = qs + ii * AT_PAD + d4 * 4;
        dst[0] = vv.x; dst[1] = vv.y; dst[2] = vv.z; dst[3] = vv.w;
    }

    float mrow[4], lrow[4], O[4][4];
#pragma unroll
    for (int r = 0; r < 4; r++) {
        mrow[r] = -3.0e38f;
        lrow[r] = 0.f;
#pragma unroll
        for (int c = 0; c < 4; c++) O[r][c] = 0.f;
    }

    for (int j0 = 0; j0 < NJ; j0 += 64) {
        __syncthreads();
#pragma unroll
        for (int p = 0; p < 4; p++) {
            int slot = tid + 256 * p;
            int jj = slot >> 4;
            int d4 = slot & 15;
            float4 kv = *(const float4*)(k + (size_t)(j0 + jj) * CS + h * HD + d4 * 4);
            float* kd = ks + jj * AT_PAD + d4 * 4;
            kd[0] = kv.x; kd[1] = kv.y; kd[2] = kv.z; kd[3] = kv.w;
            float4 vv = *(const float4*)(v + (size_t)(j0 + jj) * CS + h * HD + d4 * 4);
            vsT[(d4 * 4 + 0) * AT_PAD + jj] = vv.x;
            vsT[(d4 * 4 + 1) * AT_PAD + jj] = vv.y;
            vsT[(d4 * 4 + 2) * AT_PAD + jj] = vv.z;
            vsT[(d4 * 4 + 3) * AT_PAD + jj] = vv.w;
        }
        __syncthreads();

        float S[4][4];
#pragma unroll
        for (int r = 0; r < 4; r++)
#pragma unroll
            for (int c = 0; c < 4; c++) S[r][c] = 0.f;

#pragma unroll
        for (int d0 = 0; d0 < 64; d0 += 4) {
            float4 a4[4], b4[4];
#pragma unroll
            for (int r = 0; r < 4; r++)
                a4[r] = *(const float4*)&qs[(ty + 16 * r) * AT_PAD + d0];
#pragma unroll
            for (int c = 0; c < 4; c++)
                b4[c] = *(const float4*)&ks[(tx + 16 * c) * AT_PAD + d0];
#pragma unroll
            for (int r = 0; r < 4; r++)
#pragma unroll
                for (int c = 0; c < 4; c++) {
                    S[r][c] += a4[r].x * b4[c].x;
                    S[r][c] += a4[r].y * b4[c].y;
                    S[r][c] += a4[r].z * b4[c].z;
                    S[r][c] += a4[r].w * b4[c].w;
                }
        }

#pragma unroll
        for (int r = 0; r < 4; r++) {
            size_t zb = ((size_t)h * NI + (i0 + ty + 16 * r)) * NJ + j0;
#pragma unroll
            for (int c = 0; c < 4; c++)
                S[r][c] = S[r][c] * 0.125f + z[zb + tx + 16 * c];
        }

#pragma unroll
        for (int r = 0; r < 4; r++) {
            float mc = S[r][0];
#pragma unroll
            for (int c = 1; c < 4; c++) mc = fmaxf(mc, S[r][c]);
#pragma unroll
            for (int off = 1; off < 16; off <<= 1)
                mc = fmaxf(mc, __shfl_xor_sync(0xffffffffu, mc, off));
            float mnew = fmaxf(mrow[r], mc);
            float sc = __expf(mrow[r] - mnew);
            mrow[r] = mnew;
            lrow[r] *= sc;
#pragma unroll
            for (int c = 0; c < 4; c++) O[r][c] *= sc;
            float rs = 0.f;
#pragma unroll
            for (int c = 0; c < 4; c++) {
                S[r][c] = __expf(S[r][c] - mnew);
                rs += S[r][c];
            }
#pragma unroll
            for (int off = 1; off < 16; off <<= 1)
                rs += __shfl_xor_sync(0xffffffffu, rs, off);
            lrow[r] += rs;
        }

        __syncthreads();
#pragma unroll
        for (int r = 0; r < 4; r++)
#pragma unroll
            for (int c = 0; c < 4; c++)
                ks[(ty + 16 * r) * AT_PAD + (tx + 16 * c)] = S[r][c];
        __syncthreads();

#pragma unroll
        for (int jq = 0; jq < 64; jq += 4) {
            float4 a4[4], b4[4];
#pragma unroll
            for (int r = 0; r < 4; r++)
                a4[r] = *(const float4*)&ks[(ty + 16 * r) * AT_PAD + jq];
#pragma unroll
            for (int c = 0; c < 4; c++)
                b4[c] = *(const float4*)&vsT[(tx + 16 * c) * AT_PAD + jq];
#pragma unroll
            for (int r = 0; r < 4; r++)
#pragma unroll
                for (int c = 0; c < 4; c++) {
                    O[r][c] += a4[r].x * b4[c].x;
                    O[r][c] += a4[r].y * b4[c].y;
                    O[r][c] += a4[r].z * b4[c].z;
                    O[r][c] += a4[r].w * b4[c].w;
                }
        }
    }

#pragma unroll
    for (int r = 0; r < 4; r++) {
        float inv = 1.f / lrow[r];
        size_t ob = (size_t)(i0 + ty + 16 * r) * CS + h * HD;
#pragma unroll
        for (int c = 0; c < 4; c++)
            o[ob + tx + 16 * c] = O[r][c] * inv;
    }
}

// ---------------- launch ----------------
extern "C" void kernel_launch(void* const* d_in, const int* in_sizes, int n_in,
                              void* d_out, int out_size)
{
    const float* s    = (const float*)d_in[0];
    const float* kin  = (const float*)d_in[1];
    const float* mask = (const float*)d_in[2];
    const float* bias = (const float*)d_in[3];
    const float* Wq   = (const float*)d_in[4];
    const float* bq   = (const float*)d_in[5];
    const float* Wk   = (const float*)d_in[6];
    const float* Wv   = (const float*)d_in[7];
    const float* Wg   = (const float*)d_in[8];
    const float* Wo   = (const float*)d_in[9];
    const float* Wz   = (const float*)d_in[10];
    float* out = (float*)d_out;

    float *q, *k, *v, *g, *o, *z;
    cudaGetSymbolAddress((void**)&q, g_q);
    cudaGetSymbolAddress((void**)&k, g_k);
    cudaGetSymbolAddress((void**)&v, g_v);
    cudaGetSymbolAddress((void**)&g, g_g);
    cudaGetSymbolAddress((void**)&o, g_o);
    cudaGetSymbolAddress((void**)&z, g_z);

    __nv_bfloat16 *sh, *sl, *kh, *kl, *wqh, *wql, *wkh, *wkl,
                  *wvh, *wvl, *wgh, *wgl, *woh, *wol, *goh, *gol;
    cudaGetSymbolAddress((void**)&sh,  g_sh);  cudaGetSymbolAddress((void**)&sl,  g_sl);
    cudaGetSymbolAddress((void**)&kh,  g_kh);  cudaGetSymbolAddress((void**)&kl,  g_kl);
    cudaGetSymbolAddress((void**)&wqh, g_wqh); cudaGetSymbolAddress((void**)&wql, g_wql);
    cudaGetSymbolAddress((void**)&wkh, g_wkh); cudaGetSymbolAddress((void**)&wkl, g_wkl);
    cudaGetSymbolAddress((void**)&wvh, g_wvh); cudaGetSymbolAddress((void**)&wvl, g_wvl);
    cudaGetSymbolAddress((void**)&wgh, g_wgh); cudaGetSymbolAddress((void**)&wgl, g_wgl);
    cudaGetSymbolAddress((void**)&woh, g_woh); cudaGetSymbolAddress((void**)&wol, g_wol);
    cudaGetSymbolAddress((void**)&goh, g_goh); cudaGetSymbolAddress((void**)&gol, g_gol);

    // split 7 fp32 tensors into bf16 hi/lo
    SplitArgs sa;
    sa.src[0] = s;   sa.hi[0] = sh;  sa.lo[0] = sl;
    sa.src[1] = kin; sa.hi[1] = kh;  sa.lo[1] = kl;
    sa.src[2] = Wq;  sa.hi[2] = wqh; sa.lo[2] = wql;
    sa.src[3] = Wk;  sa.hi[3] = wkh; sa.lo[3] = wkl;
    sa.src[4] = Wv;  sa.hi[4] = wvh; sa.lo[4] = wvl;
    sa.src[5] = Wg;  sa.hi[5] = wgh; sa.lo[5] = wgl;
    sa.src[6] = Wo;  sa.hi[6] = woh; sa.lo[6] = wol;
    split7<<<dim3(256, 7), 256>>>(sa);

    cudaFuncSetAttribute(gemm_tc4, cudaFuncAttributeMaxDynamicSharedMemorySize, GEMM_SMEM);
    gemm_tc4<<<dim3(8, 8, 4), 256, GEMM_SMEM>>>(
        sh, sl, kh, kl, wqh, wql, wkh, wkl, wvh, wvl, wgh, wgl, bq, q, k, v, g);

    cudaFuncSetAttribute(zbias_kernel, cudaFuncAttributeMaxDynamicSharedMemorySize, ZB_SMEM);
    zbias_kernel<<<dim3(NI / 2, NJ / 256), 256, ZB_SMEM>>>(bias, Wz, mask, z);

    cudaFuncSetAttribute(attn_kernel, cudaFuncAttributeMaxDynamicSharedMemorySize, AT_SMEM);
    attn_kernel<<<dim3(NH, NI / 64), 256, AT_SMEM>>>(q, k, v, z, o);

    mulsplit<<<256, 256>>>(g, o, goh, gol);

    cudaFuncSetAttribute(gemm_tc_out, cudaFuncAttributeMaxDynamicSharedMemorySize, GEMM_SMEM);
    gemm_tc_out<<<dim3(8, 8), 256, GEMM_SMEM>>>(goh, gol, woh, wol, out);
}

// round 9
// speedup vs baseline: 2.3243x; 1.2021x over previous
#include <cuda_runtime.h>
#include <cuda_bf16.h>
#include <math.h>
#include <stdint.h>

#define CS 1024
#define CZ 128
#define NH 16
#define HD 64
#define NI 1024
#define NJ 1024
#define NELEM (NI * CS)

// ---------------- scratch (device globals; no allocation allowed) ----------------
__device__ float g_g[NELEM];
__device__ float g_o[NELEM];
__device__ float g_z[(size_t)NH * NI * NJ];   // 64 MB

// bf16 hi/lo split buffers (inputs + weights)
__device__ __nv_bfloat16 g_sh[NELEM],  g_sl[NELEM];     // s
__device__ __nv_bfloat16 g_xh[NELEM],  g_xl[NELEM];     // k_in
__device__ __nv_bfloat16 g_wqh[NELEM], g_wql[NELEM];
__device__ __nv_bfloat16 g_wkh[NELEM], g_wkl[NELEM];
__device__ __nv_bfloat16 g_wvh[NELEM], g_wvl[NELEM];
__device__ __nv_bfloat16 g_wgh[NELEM], g_wgl[NELEM];
__device__ __nv_bfloat16 g_woh[NELEM], g_wol[NELEM];
__device__ __nv_bfloat16 g_goh[NELEM], g_gol[NELEM];    // g (*) o
// q/k/v hi/lo (written directly by projection epilogue)
__device__ __nv_bfloat16 g_qbh[NELEM], g_qbl[NELEM];
__device__ __nv_bfloat16 g_kbh[NELEM], g_kbl[NELEM];
__device__ __nv_bfloat16 g_vbh[NELEM], g_vbl[NELEM];

// =====================================================================
// helpers (baseline PTX only — NO tcgen05 on this toolchain path)
// =====================================================================
__device__ __forceinline__ uint32_t smem_u32(const void* p) {
    uint32_t a;
    asm("{ .reg .u64 t; cvta.to.shared.u64 t, %1; cvt.u32.u64 %0, t; }"
        : "=r"(a) : "l"(p));
    return a;
}

__device__ __forceinline__ void cp16(uint32_t dst, const void* src) {
    uint64_t g;
    asm("cvta.to.global.u64 %0, %1;" : "=l"(g) : "l"(src));
    asm volatile("cp.async.cg.shared.global [%0], [%1], 16;" :: "r"(dst), "l"(g));
}

__device__ __forceinline__ void ldm_x4(uint32_t* r, uint32_t addr) {
    asm volatile("ldmatrix.sync.aligned.m8n8.x4.shared.b16 {%0,%1,%2,%3}, [%4];"
        : "=r"(r[0]), "=r"(r[1]), "=r"(r[2]), "=r"(r[3]) : "r"(addr));
}

__device__ __forceinline__ void ldm_x4t(uint32_t* r, uint32_t addr) {
    asm volatile("ldmatrix.sync.aligned.m8n8.x4.trans.shared.b16 {%0,%1,%2,%3}, [%4];"
        : "=r"(r[0]), "=r"(r[1]), "=r"(r[2]), "=r"(r[3]) : "r"(addr));
}

__device__ __forceinline__ void mma16816(float* d, const uint32_t* a, const uint32_t* b) {
    asm volatile(
        "mma.sync.aligned.m16n8k16.row.col.f32.bf16.bf16.f32 "
        "{%0,%1,%2,%3}, {%4,%5,%6,%7}, {%8,%9}, {%0,%1,%2,%3};"
        : "+f"(d[0]), "+f"(d[1]), "+f"(d[2]), "+f"(d[3])
        : "r"(a[0]), "r"(a[1]), "r"(a[2]), "r"(a[3]), "r"(b[0]), "r"(b[1]));
}

__device__ __forceinline__ uint32_t swz(uint32_t off) {
    return off ^ ((off >> 3) & 0x70);
}

// FMA-pipe exp (no MUFU): exp(x) = 2^(x*log2e), poly on [-0.5,0.5]
__device__ __forceinline__ float fexp(float x) {
    float t = fmaxf(x * 1.4426950408889634f, -126.0f);
    float zz = t + 12582912.0f;              // 1.5 * 2^23 magic round
    int   ii = __float_as_int(zz) - 0x4B400000;
    float f  = t - (zz - 12582912.0f);
    float p  = 1.3333558146e-3f;
    p = fmaf(p, f, 9.6181291076e-3f);
    p = fmaf(p, f, 5.5504108664e-2f);
    p = fmaf(p, f, 2.4022650696e-1f);
    p = fmaf(p, f, 6.9314718056e-1f);
    p = fmaf(p, f, 1.0f);
    return __int_as_float(__float_as_int(p) + (ii << 23));
}

// =====================================================================
// split conversion kernels: x -> (hi=bf16(x), lo=bf16(x-hi))
// =====================================================================
struct SplitArgs {
    const float* src[7];
    __nv_bfloat16* hi[7];
    __nv_bfloat16* lo[7];
};

__device__ __forceinline__ void split4(float4 v, __nv_bfloat162* hi2,
                                       __nv_bfloat162* lo2, size_t i) {
    __nv_bfloat16 h0 = __float2bfloat16(v.x);
    __nv_bfloat16 h1 = __float2bfloat16(v.y);
    __nv_bfloat16 h2 = __float2bfloat16(v.z);
    __nv_bfloat16 h3 = __float2bfloat16(v.w);
    __nv_bfloat16 l0 = __float2bfloat16(v.x - __bfloat162float(h0));
    __nv_bfloat16 l1 = __float2bfloat16(v.y - __bfloat162float(h1));
    __nv_bfloat16 l2 = __float2bfloat16(v.z - __bfloat162float(h2));
    __nv_bfloat16 l3 = __float2bfloat16(v.w - __bfloat162float(h3));
    __nv_bfloat162 ph0; ph0.x = h0; ph0.y = h1;
    __nv_bfloat162 ph1; ph1.x = h2; ph1.y = h3;
    __nv_bfloat162 pl0; pl0.x = l0; pl0.y = l1;
    __nv_bfloat162 pl1; pl1.x = l2; pl1.y = l3;
    hi2[2 * i] = ph0; hi2[2 * i + 1] = ph1;
    lo2[2 * i] = pl0; lo2[2 * i + 1] = pl1;
}

__global__ __launch_bounds__(256) void split7(SplitArgs a) {
    const float4* src = (const float4*)a.src[blockIdx.y];
    __nv_bfloat162* hi2 = (__nv_bfloat162*)a.hi[blockIdx.y];
    __nv_bfloat162* lo2 = (__nv_bfloat162*)a.lo[blockIdx.y];
    int t = blockIdx.x * 256 + threadIdx.x;
    for (size_t i = t; i < NELEM / 4; i += 256 * 256)
        split4(src[i], hi2, lo2, i);
}

__global__ __launch_bounds__(256) void mulsplit(
    const float* __restrict__ g, const float* __restrict__ o,
    __nv_bfloat16* hi, __nv_bfloat16* lo)
{
    const float4* g4 = (const float4*)g;
    const float4* o4 = (const float4*)o;
    __nv_bfloat162* hi2 = (__nv_bfloat162*)hi;
    __nv_bfloat162* lo2 = (__nv_bfloat162*)lo;
    int t = blockIdx.x * 256 + threadIdx.x;
    for (size_t i = t; i < NELEM / 4; i += 256 * 256) {
        float4 gv = g4[i], ov = o4[i];
        float4 v;
        v.x = gv.x * ov.x; v.y = gv.y * ov.y;
        v.z = gv.z * ov.z; v.w = gv.w * ov.w;
        split4(v, hi2, lo2, i);
    }
}

// =====================================================================
// bf16-split GEMM via mma.sync: C[m][n] = act( sum_k A[m][k]*W[n][k] (+b[n]) )
// 128x128 CTA tile, BK=64 bf16, 3-stage cp.async, 8 warps 4(M)x2(N).
// MODE: 0 plain, 1 +bias, 2 sigmoid.  OUT: 0 fp32 C, 1 bf16 hi/lo (Ch,Cl)
// =====================================================================
#define STAGE_BYTES 65536
#define GEMM_SMEM (3 * STAGE_BYTES + 1024)

__device__ __forceinline__ void load_stage(
    uint32_t sbase, int s, int tid,
    const __nv_bfloat16* Ah, const __nv_bfloat16* Al,
    const __nv_bfloat16* Bh, const __nv_bfloat16* Bl,
    int m0, int n0)
{
    uint32_t sb = sbase + (uint32_t)(s % 3) * STAGE_BYTES;
    int k0 = s * 64;
#pragma unroll
    for (int p = 0; p < 4; p++) {
        int slot = tid + 256 * p;
        int row = slot >> 3;
        int ch = slot & 7;
        uint32_t off = swz((uint32_t)(row * 128 + ch * 16));
        size_t aoff = (size_t)(m0 + row) * CS + k0 + ch * 8;
        size_t boff = (size_t)(n0 + row) * CS + k0 + ch * 8;
        cp16(sb + off,          Ah + aoff);
        cp16(sb + 16384u + off, Al + aoff);
        cp16(sb + 32768u + off, Bh + boff);
        cp16(sb + 49152u + off, Bl + boff);
    }
}

template <int MODE, int OUT>
__device__ void gemm_mma_core(
    const __nv_bfloat16* Ah, const __nv_bfloat16* Al,
    const __nv_bfloat16* Bh, const __nv_bfloat16* Bl,
    const float* bvec, float* C,
    __nv_bfloat16* Ch, __nv_bfloat16* Cl, int m0, int n0)
{
    extern __shared__ __align__(16) char dsm[];
    const int tid = threadIdx.x;
    uint32_t sbase = smem_u32(dsm);
    sbase = (sbase + 1023u) & ~1023u;

    const int w  = tid >> 5;
    const int ln = tid & 31;
    const int wm = w & 3;        // 4 warps over M: 32 rows each
    const int wn = w >> 2;       // 2 warps over N: 64 cols each

    float acc[2][8][4];
#pragma unroll
    for (int mt = 0; mt < 2; mt++)
#pragma unroll
        for (int nt = 0; nt < 8; nt++)
#pragma unroll
            for (int e = 0; e < 4; e++) acc[mt][nt][e] = 0.f;

    load_stage(sbase, 0, tid, Ah, Al, Bh, Bl, m0, n0);
    asm volatile("cp.async.commit_group;" ::: "memory");
    load_stage(sbase, 1, tid, Ah, Al, Bh, Bl, m0, n0);
    asm volatile("cp.async.commit_group;" ::: "memory");

    const int a_row = wm * 32 + (ln & 15);
    const int a_kb  = (ln >> 4) * 16;
    const int b_row = wn * 64 + (ln & 7) + ((ln >> 4) & 1) * 8;
    const int b_kb  = ((ln >> 3) & 1) * 16;

    for (int s = 0; s < 16; s++) {
        if (s < 15) asm volatile("cp.async.wait_group 1;" ::: "memory");
        else        asm volatile("cp.async.wait_group 0;" ::: "memory");
        __syncthreads();

        uint32_t sb = sbase + (uint32_t)(s % 3) * STAGE_BYTES;
#pragma unroll
        for (int kk = 0; kk < 4; kk++) {
            uint32_t ah[2][4], al[2][4], bh[8][2], bl[8][2];
#pragma unroll
            for (int mt = 0; mt < 2; mt++) {
                uint32_t off = swz((uint32_t)((a_row + mt * 16) * 128 + kk * 32 + a_kb));
                ldm_x4(ah[mt], sb + off);
                ldm_x4(al[mt], sb + 16384u + off);
            }
#pragma unroll
            for (int np = 0; np < 4; np++) {
                uint32_t off = swz((uint32_t)((b_row + np * 16) * 128 + kk * 32 + b_kb));
                uint32_t t4[4];
                ldm_x4(t4, sb + 32768u + off);
                bh[2 * np][0] = t4[0]; bh[2 * np][1] = t4[1];
                bh[2 * np + 1][0] = t4[2]; bh[2 * np + 1][1] = t4[3];
                ldm_x4(t4, sb + 49152u + off);
                bl[2 * np][0] = t4[0]; bl[2 * np][1] = t4[1];
                bl[2 * np + 1][0] = t4[2]; bl[2 * np + 1][1] = t4[3];
            }
#pragma unroll
            for (int mt = 0; mt < 2; mt++)
#pragma unroll
                for (int nt = 0; nt < 8; nt++) {
                    mma16816(acc[mt][nt], ah[mt], bh[nt]);
                    mma16816(acc[mt][nt], al[mt], bh[nt]);
                    mma16816(acc[mt][nt], ah[mt], bl[nt]);
                }
        }

        if (s + 2 < 16) {
            load_stage(sbase, s + 2, tid, Ah, Al, Bh, Bl, m0, n0);
            asm volatile("cp.async.commit_group;" ::: "memory");
        }
    }

    const int er = ln >> 2;
    const int ec = (ln & 3) * 2;
#pragma unroll
    for (int mt = 0; mt < 2; mt++) {
#pragma unroll
        for (int nt = 0; nt < 8; nt++) {
            int m = m0 + wm * 32 + mt * 16 + er;
            int n = n0 + wn * 64 + nt * 8 + ec;
#pragma unroll
            for (int half = 0; half < 2; half++) {
                float2 r;
                r.x = acc[mt][nt][2 * half + 0];
                r.y = acc[mt][nt][2 * half + 1];
                if (MODE == 1) { r.x += bvec[n]; r.y += bvec[n + 1]; }
                else if (MODE == 2) {
                    r.x = 1.f / (1.f + __expf(-r.x));
                    r.y = 1.f / (1.f + __expf(-r.y));
                }
                size_t idx = (size_t)(m + half * 8) * CS + n;
                if (OUT == 0) {
                    *(float2*)(C + idx) = r;
                } else {
                    __nv_bfloat16 h0 = __float2bfloat16(r.x);
                    __nv_bfloat16 h1 = __float2bfloat16(r.y);
                    __nv_bfloat16 l0 = __float2bfloat16(r.x - __bfloat162float(h0));
                    __nv_bfloat16 l1 = __float2bfloat16(r.y - __bfloat162float(h1));
                    __nv_bfloat162 hh; hh.x = h0; hh.y = h1;
                    __nv_bfloat162 ll; ll.x = l0; ll.y = l1;
                    *(__nv_bfloat162*)(Ch + idx) = hh;
                    *(__nv_bfloat162*)(Cl + idx) = ll;
                }
            }
        }
    }
}

// Fused 4 projections: z = 0:q(+bq)->bf16, 1:k->bf16, 2:v->bf16, 3:g(sigmoid)->fp32
__global__ __launch_bounds__(256, 1) void gemm_tc4(
    const __nv_bfloat16* sh,  const __nv_bfloat16* sl,
    const __nv_bfloat16* xh,  const __nv_bfloat16* xl,
    const __nv_bfloat16* wqh, const __nv_bfloat16* wql,
    const __nv_bfloat16* wkh, const __nv_bfloat16* wkl,
    const __nv_bfloat16* wvh, const __nv_bfloat16* wvl,
    const __nv_bfloat16* wgh, const __nv_bfloat16* wgl,
    const float* bq,
    __nv_bfloat16* qbh, __nv_bfloat16* qbl,
    __nv_bfloat16* kbh, __nv_bfloat16* kbl,
    __nv_bfloat16* vbh, __nv_bfloat16* vbl,
    float* g)
{
    int m0 = blockIdx.y * 128, n0 = blockIdx.x * 128;
    switch (blockIdx.z) {
        case 0:  gemm_mma_core<1, 1>(sh, sl, wqh, wql, bq, nullptr, qbh, qbl, m0, n0); break;
        case 1:  gemm_mma_core<0, 1>(xh, xl, wkh, wkl, nullptr, nullptr, kbh, kbl, m0, n0); break;
        case 2:  gemm_mma_core<0, 1>(xh, xl, wvh, wvl, nullptr, nullptr, vbh, vbl, m0, n0); break;
        default: gemm_mma_core<2, 0>(sh, sl, wgh, wgl, nullptr, g, nullptr, nullptr, m0, n0); break;
    }
}

__global__ __launch_bounds__(256, 1) void gemm_tc_out(
    const __nv_bfloat16* ah, const __nv_bfloat16* al,
    const __nv_bfloat16* bh, const __nv_bfloat16* bl,
    float* out)
{
    gemm_mma_core<0, 0>(ah, al, bh, bl, nullptr, out, nullptr, nullptr,
                        blockIdx.y * 128, blockIdx.x * 128);
}

// ---------------- z kernel: z[h,i,j] = sum_c bias[i,j,c]*Wz[c,h] + (1-mask[j])*(-1e6)
#define ZB_SMEM ((2 * 256 * 33 + CZ * NH) * 4)
__global__ __launch_bounds__(256) void zbias_kernel(
    const float* __restrict__ bias, const float* __restrict__ Wz,
    const float* __restrict__ mask, float* __restrict__ z)
{
    extern __shared__ float sm[];
    float* bs = sm;                      // [2][256][33]
    float* wzs = sm + 2 * 256 * 33;      // [128][16]

    const int tid = threadIdx.x;
    const int jg = tid & 31;
    const int hg = (tid >> 5) & 3;
    const int ig = tid >> 7;
    const int i0 = blockIdx.x * 2;
    const int j0 = blockIdx.y * 256;

    for (int t = tid; t < CZ * NH; t += 256) wzs[t] = Wz[t];

    float acc[8][4];
#pragma unroll
    for (int kk = 0; kk < 8; kk++)
#pragma unroll
        for (int hh = 0; hh < 4; hh++) acc[kk][hh] = 0.f;

    for (int cc = 0; cc < CZ; cc += 32) {
        __syncthreads();
#pragma unroll
        for (int p = 0; p < 16; p++) {
            int slot = tid + 256 * p;
            int c4 = slot & 7;
            int row = slot >> 3;
            int ii = row >> 8;
            int j = row & 255;
            float4 vv = *(const float4*)(bias +
                ((size_t)(i0 + ii) * NJ + (j0 + j)) * CZ + cc + c4 * 4);
            float* dst = bs + ((size_t)ii * 256 + j) * 33 + c4 * 4;
            dst[0] = vv.x; dst[1] = vv.y; dst[2] = vv.z; dst[3] = vv.w;
        }
        __syncthreads();

#pragma unroll
        for (int c = 0; c < 32; c++) {
            const float* wrow = wzs + (cc + c) * NH + hg * 4;
            float w0 = wrow[0], w1 = wrow[1], w2 = wrow[2], w3 = wrow[3];
#pragma unroll
            for (int kk = 0; kk < 8; kk++) {
                float bv = bs[((size_t)ig * 256 + (jg + 32 * kk)) * 33 + c];
                acc[kk][0] += bv * w0;
                acc[kk][1] += bv * w1;
                acc[kk][2] += bv * w2;
                acc[kk][3] += bv * w3;
            }
        }
    }

    const int i = i0 + ig;
#pragma unroll
    for (int hh = 0; hh < 4; hh++) {
        int h = hg * 4 + hh;
        size_t base = ((size_t)h * NI + i) * NJ;
#pragma unroll
        for (int kk = 0; kk < 8; kk++) {
            int j = j0 + jg + 32 * kk;
            z[base + j] = acc[kk][hh] + (1.f - mask[j]) * (-1000000.0f);
        }
    }
}

// =====================================================================
// Tensor-core flash attention: CTA = (head, 64 i-rows); j tiled by 64.
// QK: q/k hi/lo 3-term mma; softmax SIMT w/ FMA exp; P split hi/lo in smem;
// PV: ldmatrix.trans for V. 8 warps as 2(M:32) x 4(N:16).
// =====================================================================
#define ATQ_H 0
#define ATQ_L 8192
#define ATK_H 16384
#define ATK_L 24576
#define ATV_H 32768
#define ATV_L 40960
#define ATSS  49152               /* 64 x 68 fp32 = 17408 */
#define ATP_H 66560
#define ATP_L 74752
#define ATM   82944
#define ATL   83200
#define ATSC  83456
#define AT_SMEM 83712

__global__ __launch_bounds__(256, 2) void attn_mma(
    const __nv_bfloat16* __restrict__ qh_g, const __nv_bfloat16* __restrict__ ql_g,
    const __nv_bfloat16* __restrict__ kh_g, const __nv_bfloat16* __restrict__ kl_g,
    const __nv_bfloat16* __restrict__ vh_g, const __nv_bfloat16* __restrict__ vl_g,
    const float* __restrict__ z, float* __restrict__ o)
{
    extern __shared__ __align__(16) char smra[];
    uint32_t sb = smem_u32(smra);
    const int h = blockIdx.x;
    const int i0 = blockIdx.y * 64;
    const int tid = threadIdx.x;
    const int w = tid >> 5, ln = tid & 31;
    const int wm = w & 1;        // 2 warps over M (32 rows)
    const int wn = w >> 1;       // 4 warps over N (16 cols)
    const int er = ln >> 2, ec = (ln & 3) * 2;

    // load Q hi/lo tiles (64 x 64 bf16 each)
#pragma unroll
    for (int p = 0; p < 4; p++) {
        int slot = tid + 256 * p;
        int arr = slot >> 9, idx = slot & 511;
        int row = idx >> 3, ch = idx & 7;
        const __nv_bfloat16* src = (arr ? ql_g : qh_g)
            + (size_t)(i0 + row) * CS + h * HD + ch * 8;
        cp16(sb + (arr ? ATQ_L : ATQ_H) + swz((uint32_t)(row * 128 + ch * 16)), src);
    }
    asm volatile("cp.async.commit_group;" ::: "memory");

    if (tid < 64) {
        *(float*)(smra + ATM + tid * 4) = -3.0e38f;
        *(float*)(smra + ATL + tid * 4) = 0.f;
    }

    float accO[2][2][4];
#pragma unroll
    for (int mt = 0; mt < 2; mt++)
#pragma unroll
        for (int nt = 0; nt < 2; nt++)
#pragma unroll
            for (int e = 0; e < 4; e++) accO[mt][nt][e] = 0.f;

    for (int jt = 0; jt < 16; jt++) {
        const int j0 = jt * 64;
        __syncthreads();   // previous tile's smem reads done before overwrite

        // load K/V hi/lo tiles (4 x 64 x 64 bf16)
#pragma unroll
        for (int p = 0; p < 8; p++) {
            int slot = tid + 256 * p;
            int arr = slot >> 9, idx = slot & 511;
            int row = idx >> 3, ch = idx & 7;
            const __nv_bfloat16* base =
                (arr == 0) ? kh_g : (arr == 1) ? kl_g : (arr == 2) ? vh_g : vl_g;
            cp16(sb + ATK_H + arr * 8192 + swz((uint32_t)(row * 128 + ch * 16)),
                 base + (size_t)(j0 + row) * CS + h * HD + ch * 8);
        }
        asm volatile("cp.async.commit_group;" ::: "memory");
        asm volatile("cp.async.wait_group 0;" ::: "memory");
        __syncthreads();

        // ---- QK: S = Q @ K^T (3-term) ----
        float accS[2][2][4];
#pragma unroll
        for (int mt = 0; mt < 2; mt++)
#pragma unroll
            for (int nt = 0; nt < 2; nt++)
#pragma unroll
                for (int e = 0; e < 4; e++) accS[mt][nt][e] = 0.f;

#pragma unroll
        for (int kk = 0; kk < 4; kk++) {
            uint32_t qa[2][4], ql2[2][4];
#pragma unroll
            for (int mt = 0; mt < 2; mt++) {
                uint32_t off = swz((uint32_t)((wm * 32 + mt * 16 + (ln & 15)) * 128
                                              + kk * 32 + (ln >> 4) * 16));
                ldm_x4(qa[mt],  sb + ATQ_H + off);
                ldm_x4(ql2[mt], sb + ATQ_L + off);
            }
            uint32_t off = swz((uint32_t)((wn * 16 + (ln & 7) + ((ln >> 4) & 1) * 8) * 128
                                          + kk * 32 + ((ln >> 3) & 1) * 16));
            uint32_t th[4], tl[4];
            ldm_x4(th, sb + ATK_H + off);
            ldm_x4(tl, sb + ATK_L + off);
#pragma unroll
            for (int mt = 0; mt < 2; mt++) {
                mma16816(accS[mt][0], qa[mt],  th);
                mma16816(accS[mt][0], ql2[mt], th);
                mma16816(accS[mt][0], qa[mt],  tl);
                mma16816(accS[mt][1], qa[mt],  th + 2);
                mma16816(accS[mt][1], ql2[mt], th + 2);
                mma16816(accS[mt][1], qa[mt],  tl + 2);
            }
        }

        // write S frags to smem (raw)
#pragma unroll
        for (int mt = 0; mt < 2; mt++)
#pragma unroll
            for (int nt = 0; nt < 2; nt++) {
                int row = wm * 32 + mt * 16 + er;
                int col = wn * 16 + nt * 8 + ec;
                float2 v0; v0.x = accS[mt][nt][0]; v0.y = accS[mt][nt][1];
                float2 v1; v1.x = accS[mt][nt][2]; v1.y = accS[mt][nt][3];
                *(float2*)(smra + ATSS + ((row) * 68 + col) * 4) = v0;
                *(float2*)(smra + ATSS + ((row + 8) * 68 + col) * 4) = v1;
            }
        __syncthreads();

        // ---- softmax (4 threads / row, FMA exp) ----
        {
            const int r = tid >> 2, qd = tid & 3;
            const float* Ssr = (const float*)(smra + ATSS) + r * 68 + qd * 16;
            const float* zr = z + ((size_t)h * NI + i0 + r) * NJ + j0 + qd * 16;
            float vals[16];
            float mx = -3.0e38f;
#pragma unroll
            for (int u = 0; u < 4; u++) {
                float4 sv = *(const float4*)(Ssr + 4 * u);
                float4 zv = *(const float4*)(zr + 4 * u);
                vals[4 * u + 0] = fmaf(sv.x, 0.125f, zv.x);
                vals[4 * u + 1] = fmaf(sv.y, 0.125f, zv.y);
                vals[4 * u + 2] = fmaf(sv.z, 0.125f, zv.z);
                vals[4 * u + 3] = fmaf(sv.w, 0.125f, zv.w);
#pragma unroll
                for (int e = 0; e < 4; e++) mx = fmaxf(mx, vals[4 * u + e]);
            }
            mx = fmaxf(mx, __shfl_xor_sync(0xffffffffu, mx, 1));
            mx = fmaxf(mx, __shfl_xor_sync(0xffffffffu, mx, 2));
            float mold = ((const float*)(smra + ATM))[r];
            float mnew = fmaxf(mold, mx);
            float sum = 0.f;
#pragma unroll
            for (int u = 0; u < 16; u += 2) {
                float p0 = fexp(vals[u] - mnew);
                float p1 = fexp(vals[u + 1] - mnew);
                sum += p0 + p1;
                __nv_bfloat16 h0 = __float2bfloat16(p0);
                __nv_bfloat16 h1 = __float2bfloat16(p1);
                __nv_bfloat16 l0 = __float2bfloat16(p0 - __bfloat162float(h0));
                __nv_bfloat16 l1 = __float2bfloat16(p1 - __bfloat162float(h1));
                __nv_bfloat162 hh; hh.x = h0; hh.y = h1;
                __nv_bfloat162 llv; llv.x = l0; llv.y = l1;
                uint32_t off = swz((uint32_t)(r * 128 + qd * 32 + u * 2));
                *(__nv_bfloat162*)(smra + ATP_H + off) = hh;
                *(__nv_bfloat162*)(smra + ATP_L + off) = llv;
            }
            sum += __shfl_xor_sync(0xffffffffu, sum, 1);
            sum += __shfl_xor_sync(0xffffffffu, sum, 2);
            if (qd == 0) {
                float sc = fexp(mold - mnew);
                ((float*)(smra + ATM))[r] = mnew;
                ((float*)(smra + ATSC))[r] = sc;
                float* lp = (float*)(smra + ATL);
                lp[r] = lp[r] * sc + sum;
            }
        }
        __syncthreads();

        // ---- rescale O, then PV: O += P @ V (3-term, V via ldmatrix.trans) ----
        {
            const float* scp = (const float*)(smra + ATSC);
#pragma unroll
            for (int mt = 0; mt < 2; mt++) {
                float s0 = scp[wm * 32 + mt * 16 + er];
                float s1 = scp[wm * 32 + mt * 16 + er + 8];
#pragma unroll
                for (int nt = 0; nt < 2; nt++) {
                    accO[mt][nt][0] *= s0; accO[mt][nt][1] *= s0;
                    accO[mt][nt][2] *= s1; accO[mt][nt][3] *= s1;
                }
            }
        }
#pragma unroll
        for (int kk = 0; kk < 4; kk++) {
            uint32_t pa[2][4], pl2[2][4];
#pragma unroll
            for (int mt = 0; mt < 2; mt++) {
                uint32_t off = swz((uint32_t)((wm * 32 + mt * 16 + (ln & 15)) * 128
                                              + kk * 32 + (ln >> 4) * 16));
                ldm_x4(pa[mt],  sb + ATP_H + off);
                ldm_x4(pl2[mt], sb + ATP_L + off);
            }
            uint32_t offv = swz((uint32_t)((kk * 16 + (ln & 7) + ((ln >> 3) & 1) * 8) * 128
                                           + (wn * 16 + ((ln >> 4) & 1) * 8) * 2));
            uint32_t th[4], tl[4];
            ldm_x4t(th, sb + ATV_H + offv);
            ldm_x4t(tl, sb + ATV_L + offv);
#pragma unroll
            for (int mt = 0; mt < 2; mt++) {
                mma16816(accO[mt][0], pa[mt],  th);
                mma16816(accO[mt][0], pl2[mt], th);
                mma16816(accO[mt][0], pa[mt],  tl);
                mma16816(accO[mt][1], pa[mt],  th + 2);
                mma16816(accO[mt][1], pl2[mt], th + 2);
                mma16816(accO[mt][1], pa[mt],  tl + 2);
            }
        }
    }

    __syncthreads();
    const float* lp = (const float*)(smra + ATL);
#pragma unroll
    for (int mt = 0; mt < 2; mt++) {
        float inv0 = 1.f / lp[wm * 32 + mt * 16 + er];
        float inv1 = 1.f / lp[wm * 32 + mt * 16 + er + 8];
#pragma unroll
        for (int nt = 0; nt < 2; nt++) {
            int row = i0 + wm * 32 + mt * 16 + er;
            int col = wn * 16 + nt * 8 + ec;
            float2 r0; r0.x = accO[mt][nt][0] * inv0; r0.y = accO[mt][nt][1] * inv0;
            float2 r1; r1.x = accO[mt][nt][2] * inv1; r1.y = accO[mt][nt][3] * inv1;
            *(float2*)(o + (size_t)row * CS + h * HD + col) = r0;
            *(float2*)(o + (size_t)(row + 8) * CS + h * HD + col) = r1;
        }
    }
}

// ---------------- launch ----------------
extern "C" void kernel_launch(void* const* d_in, const int* in_sizes, int n_in,
                              void* d_out, int out_size)
{
    const float* s    = (const float*)d_in[0];
    const float* kin  = (const float*)d_in[1];
    const float* mask = (const float*)d_in[2];
    const float* bias = (const float*)d_in[3];
    const float* Wq   = (const float*)d_in[4];
    const float* bq   = (const float*)d_in[5];
    const float* Wk   = (const float*)d_in[6];
    const float* Wv   = (const float*)d_in[7];
    const float* Wg   = (const float*)d_in[8];
    const float* Wo   = (const float*)d_in[9];
    const float* Wz   = (const float*)d_in[10];
    float* out = (float*)d_out;

    float *g, *o, *z;
    cudaGetSymbolAddress((void**)&g, g_g);
    cudaGetSymbolAddress((void**)&o, g_o);
    cudaGetSymbolAddress((void**)&z, g_z);

    __nv_bfloat16 *sh, *sl, *xh, *xl, *wqh, *wql, *wkh, *wkl,
                  *wvh, *wvl, *wgh, *wgl, *woh, *wol, *goh, *gol,
                  *qbh, *qbl, *kbh, *kbl, *vbh, *vbl;
    cudaGetSymbolAddress((void**)&sh,  g_sh);  cudaGetSymbolAddress((void**)&sl,  g_sl);
    cudaGetSymbolAddress((void**)&xh,  g_xh);  cudaGetSymbolAddress((void**)&xl,  g_xl);
    cudaGetSymbolAddress((void**)&wqh, g_wqh); cudaGetSymbolAddress((void**)&wql, g_wql);
    cudaGetSymbolAddress((void**)&wkh, g_wkh); cudaGetSymbolAddress((void**)&wkl, g_wkl);
    cudaGetSymbolAddress((void**)&wvh, g_wvh); cudaGetSymbolAddress((void**)&wvl, g_wvl);
    cudaGetSymbolAddress((void**)&wgh, g_wgh); cudaGetSymbolAddress((void**)&wgl, g_wgl);
    cudaGetSymbolAddress((void**)&woh, g_woh); cudaGetSymbolAddress((void**)&wol, g_wol);
    cudaGetSymbolAddress((void**)&goh, g_goh); cudaGetSymbolAddress((void**)&gol, g_gol);
    cudaGetSymbolAddress((void**)&qbh, g_qbh); cudaGetSymbolAddress((void**)&qbl, g_qbl);
    cudaGetSymbolAddress((void**)&kbh, g_kbh); cudaGetSymbolAddress((void**)&kbl, g_kbl);
    cudaGetSymbolAddress((void**)&vbh, g_vbh); cudaGetSymbolAddress((void**)&vbl, g_vbl);

    SplitArgs sa;
    sa.src[0] = s;   sa.hi[0] = sh;  sa.lo[0] = sl;
    sa.src[1] = kin; sa.hi[1] = xh;  sa.lo[1] = xl;
    sa.src[2] = Wq;  sa.hi[2] = wqh; sa.lo[2] = wql;
    sa.src[3] = Wk;  sa.hi[3] = wkh; sa.lo[3] = wkl;
    sa.src[4] = Wv;  sa.hi[4] = wvh; sa.lo[4] = wvl;
    sa.src[5] = Wg;  sa.hi[5] = wgh; sa.lo[5] = wgl;
    sa.src[6] = Wo;  sa.hi[6] = woh; sa.lo[6] = wol;
    split7<<<dim3(256, 7), 256>>>(sa);

    cudaFuncSetAttribute(gemm_tc4, cudaFuncAttributeMaxDynamicSharedMemorySize, GEMM_SMEM);
    gemm_tc4<<<dim3(8, 8, 4), 256, GEMM_SMEM>>>(
        sh, sl, xh, xl, wqh, wql, wkh, wkl, wvh, wvl, wgh, wgl, bq,
        qbh, qbl, kbh, kbl, vbh, vbl, g);

    cudaFuncSetAttribute(zbias_kernel, cudaFuncAttributeMaxDynamicSharedMemorySize, ZB_SMEM);
    zbias_kernel<<<dim3(NI / 2, NJ / 256), 256, ZB_SMEM>>>(bias, Wz, mask, z);

    cudaFuncSetAttribute(attn_mma, cudaFuncAttributeMaxDynamicSharedMemorySize, AT_SMEM);
    attn_mma<<<dim3(NH, NI / 64), 256, AT_SMEM>>>(qbh, qbl, kbh, kbl, vbh, vbl, z, o);

    mulsplit<<<256, 256>>>(g, o, goh, gol);

    cudaFuncSetAttribute(gemm_tc_out, cudaFuncAttributeMaxDynamicSharedMemorySize, GEMM_SMEM);
    gemm_tc_out<<<dim3(8, 8), 256, GEMM_SMEM>>>(goh, gol, woh, wol, out);
}